// round 13
// baseline (speedup 1.0000x reference)
#include <cuda_runtime.h>
#include <cuda_bf16.h>
#include <cstdint>

typedef unsigned long long u64;

// ---------------------------------------------------------------------------
// Problem constants
// ---------------------------------------------------------------------------
#define SEQ   512
#define BATCH 64
#define HID   1024
#define G4    4096
#define MROWS (SEQ * BATCH)   // 32768

// ---------------------------------------------------------------------------
// Scratch (device globals)
// ---------------------------------------------------------------------------
__device__ float g_proj[(size_t)MROWS * G4];          // [T*B, 4H] x-projection
__device__ __align__(16) __nv_bfloat16 g_Ahi[(size_t)MROWS * HID];
__device__ __align__(16) __nv_bfloat16 g_Alo[(size_t)MROWS * HID];
__device__ __align__(16) __nv_bfloat16 g_Whi[(size_t)G4 * HID];
__device__ __align__(16) __nv_bfloat16 g_Wlo[(size_t)G4 * HID];
__device__ __align__(16) __nv_bfloat16 g_hh[3][BATCH * HID];   // h hi, [b][j]
__device__ __align__(16) __nv_bfloat16 g_hl[3][BATCH * HID];   // h lo, [b][j]
__device__ unsigned g_done[32];                                // per-group h publish

// ---------------------------------------------------------------------------
// Helpers
// ---------------------------------------------------------------------------
__device__ __forceinline__ uint32_t smem_u32(const void* p) {
    uint32_t a;
    asm("{ .reg .u64 t; cvta.to.shared.u64 t, %1; cvt.u32.u64 %0, t; }"
        : "=r"(a) : "l"(p));
    return a;
}
__device__ __forceinline__ void ldsm4(uint32_t* r, uint32_t addr) {
    asm volatile("ldmatrix.sync.aligned.m8n8.x4.shared.b16 {%0,%1,%2,%3}, [%4];"
                 : "=r"(r[0]), "=r"(r[1]), "=r"(r[2]), "=r"(r[3]) : "r"(addr));
}
__device__ __forceinline__ void ldsm2(uint32_t* r, uint32_t addr) {
    asm volatile("ldmatrix.sync.aligned.m8n8.x2.shared.b16 {%0,%1}, [%2];"
                 : "=r"(r[0]), "=r"(r[1]) : "r"(addr));
}
__device__ __forceinline__ void mma16816(float* c, const uint32_t* a, const uint32_t* b) {
    asm volatile("mma.sync.aligned.m16n8k16.row.col.f32.bf16.bf16.f32 "
                 "{%0,%1,%2,%3}, {%4,%5,%6,%7}, {%8,%9}, {%0,%1,%2,%3};"
                 : "+f"(c[0]), "+f"(c[1]), "+f"(c[2]), "+f"(c[3])
                 : "r"(a[0]), "r"(a[1]), "r"(a[2]), "r"(a[3]),
                   "r"(b[0]), "r"(b[1]));
}
#define CP_ASYNC16(sdst, gsrc) \
    asm volatile("cp.async.cg.shared.global [%0], [%1], 16;" :: "r"(sdst), "l"(gsrc))
#define CP_COMMIT() asm volatile("cp.async.commit_group;" ::: "memory")
#define CP_WAIT0()  asm volatile("cp.async.wait_group 0;" ::: "memory")
#define CP_WAIT1()  asm volatile("cp.async.wait_group 1;" ::: "memory")

#define CLUSTER_ARRIVE() asm volatile("barrier.cluster.arrive.aligned;" ::: "memory")
#define CLUSTER_WAIT()   asm volatile("barrier.cluster.wait.aligned;" ::: "memory")

__device__ __forceinline__ uint32_t mapa_rank(uint32_t addr, int rank) {
    uint32_t r;
    asm("mapa.shared::cluster.u32 %0, %1, %2;" : "=r"(r) : "r"(addr), "r"(rank));
    return r;
}
__device__ __forceinline__ void sts_cluster64(uint32_t addr, float a, float b) {
    u64 v; asm("mov.b64 %0, {%1,%2};" : "=l"(v) : "f"(a), "f"(b));
    asm volatile("st.shared::cluster.b64 [%0], %1;" :: "r"(addr), "l"(v) : "memory");
}

__device__ __forceinline__ float sigmoidf_(float x) { return 1.0f / (1.0f + __expf(-x)); }
__device__ __forceinline__ float tanhf_(float x) { return 2.0f / (1.0f + __expf(-2.0f * x)) - 1.0f; }

// ---------------------------------------------------------------------------
// Zero h buffer 0 + counters
// ---------------------------------------------------------------------------
__global__ void zero_state_kernel() {
    int i = blockIdx.x * blockDim.x + threadIdx.x;
    if (i < 32) g_done[i] = 0u;
    const uint4 z = make_uint4(0, 0, 0, 0);
    if (i < (BATCH * HID * 2) / 16) {
        reinterpret_cast<uint4*>(&g_hh[0][0])[i] = z;
        reinterpret_cast<uint4*>(&g_hl[0][0])[i] = z;
    }
}

// ---------------------------------------------------------------------------
// fp32 -> bf16 hi/lo split
// ---------------------------------------------------------------------------
__global__ void split_kernel(const float* __restrict__ src,
                             __nv_bfloat16* __restrict__ hi,
                             __nv_bfloat16* __restrict__ lo, int n4) {
    int i = blockIdx.x * blockDim.x + threadIdx.x;
    int stride = gridDim.x * blockDim.x;
    for (; i < n4; i += stride) {
        float4 v = reinterpret_cast<const float4*>(src)[i];
        __nv_bfloat16 h[4], l[4];
        float vv[4] = {v.x, v.y, v.z, v.w};
#pragma unroll
        for (int k = 0; k < 4; k++) {
            h[k] = __float2bfloat16_rn(vv[k]);
            l[k] = __float2bfloat16_rn(vv[k] - __bfloat162float(h[k]));
        }
        reinterpret_cast<uint2*>(hi)[i] = *reinterpret_cast<uint2*>(h);
        reinterpret_cast<uint2*>(lo)[i] = *reinterpret_cast<uint2*>(l);
    }
}

// ---------------------------------------------------------------------------
// bf16x3 GEMM via mma.sync — 256 threads, 8 warps (4m x 2n), 2-stage
// cp.async ring, 80KB SMEM -> 2 CTAs/SM co-resident.  (R10, proven)
// ---------------------------------------------------------------------------
#define KSTG       32
#define NSTAGES    (HID / KSTG)
#define PITCH_B    80
#define REG_BYTES  (128 * PITCH_B)
#define STG_BYTES  (4 * REG_BYTES)       // 40960
#define GEMM_SMEM  (2 * STG_BYTES)       // 81920 -> 2 CTAs/SM

__device__ __forceinline__ void stage_load(uint32_t sbase, int s, int m0, int n0,
                                           int tid) {
    const int kt = s * KSTG;
    const uint32_t dst = sbase + (s & 1) * STG_BYTES;
#pragma unroll
    for (int r = 0; r < 4; r++) {
        const __nv_bfloat16* src =
            (r == 0) ? g_Ahi : (r == 1) ? g_Alo : (r == 2) ? g_Whi : g_Wlo;
        const int rb = (r < 2) ? m0 : n0;
#pragma unroll
        for (int j = 0; j < 2; j++) {
            const int chunk = tid + j * 256;
            const int row = chunk >> 2;
            const int kc = chunk & 3;
            const void* g = src + (size_t)(rb + row) * HID + kt + kc * 8;
            const uint32_t sd = dst + r * REG_BYTES + row * PITCH_B + kc * 16;
            CP_ASYNC16(sd, g);
        }
    }
}

__global__ __launch_bounds__(256, 2) void mma_gemm_kernel(
    const float* __restrict__ bias1, const float* __restrict__ bias2)
{
    extern __shared__ char dsm[];
    __shared__ float s_bias[128];

    const int tid = threadIdx.x;
    const int wid = tid >> 5;
    const int lane = tid & 31;
    const int m0 = blockIdx.x * 128;
    const int n0 = blockIdx.y * 128;
    const int wm = (wid & 3) * 32;
    const int wn = (wid >> 2) * 64;

    const uint32_t sbase = smem_u32(dsm);

    if (tid < 128) s_bias[tid] = bias1[n0 + tid] + bias2[n0 + tid];

    float acc[2][8][4];
#pragma unroll
    for (int ma = 0; ma < 2; ma++)
#pragma unroll
        for (int nb = 0; nb < 8; nb++)
#pragma unroll
            for (int c = 0; c < 4; c++) acc[ma][nb][c] = 0.f;

    stage_load(sbase, 0, m0, n0, tid);
    CP_COMMIT();

    for (int s = 0; s < NSTAGES; s++) {
        if (s + 1 < NSTAGES) stage_load(sbase, s + 1, m0, n0, tid);
        CP_COMMIT();
        CP_WAIT1();
        __syncthreads();

        const uint32_t sb = sbase + (s & 1) * STG_BYTES;
        const uint32_t aHi = sb;
        const uint32_t aLo = sb + REG_BYTES;
        const uint32_t wHi = sb + 2 * REG_BYTES;
        const uint32_t wLo = sb + 3 * REG_BYTES;

#pragma unroll
        for (int kk = 0; kk < 2; kk++) {
            const uint32_t aoff = (lane & 15) * PITCH_B + (lane >> 4) * 16 + kk * 32;
            const uint32_t boff = (lane & 7) * PITCH_B + ((lane >> 3) & 1) * 16 + kk * 32;

            uint32_t ahi[2][4], alo[2][4];
            ldsm4(ahi[0], aHi + (wm + 0) * PITCH_B + aoff);
            ldsm4(ahi[1], aHi + (wm + 16) * PITCH_B + aoff);
            ldsm4(alo[0], aLo + (wm + 0) * PITCH_B + aoff);
            ldsm4(alo[1], aLo + (wm + 16) * PITCH_B + aoff);

            uint32_t whi[8][2], wlo[8][2];
#pragma unroll
            for (int nb = 0; nb < 8; nb++) {
                ldsm2(whi[nb], wHi + (wn + nb * 8) * PITCH_B + boff);
                ldsm2(wlo[nb], wLo + (wn + nb * 8) * PITCH_B + boff);
            }

#pragma unroll
            for (int ma = 0; ma < 2; ma++)
#pragma unroll
                for (int nb = 0; nb < 8; nb++) {
                    mma16816(acc[ma][nb], ahi[ma], whi[nb]);
                    mma16816(acc[ma][nb], ahi[ma], wlo[nb]);
                    mma16816(acc[ma][nb], alo[ma], whi[nb]);
                }
        }
        __syncthreads();
    }

#pragma unroll
    for (int ma = 0; ma < 2; ma++) {
        const int row = m0 + wm + ma * 16 + (lane >> 2);
#pragma unroll
        for (int nb = 0; nb < 8; nb++) {
            const int cloc = wn + nb * 8 + (lane & 3) * 2;
            const int col = n0 + cloc;
            const float b0 = s_bias[cloc], b1 = s_bias[cloc + 1];
            float2 v0 = make_float2(acc[ma][nb][0] + b0, acc[ma][nb][1] + b1);
            float2 v1 = make_float2(acc[ma][nb][2] + b0, acc[ma][nb][3] + b1);
            *reinterpret_cast<float2*>(&g_proj[(size_t)row * G4 + col]) = v0;
            *reinterpret_cast<float2*>(&g_proj[(size_t)(row + 8) * G4 + col]) = v1;
        }
    }
}

// ---------------------------------------------------------------------------
// Persistent LSTM recurrence — split-K + cluster DSMEM exchange (R12 base)
// + chunked h staging overlapped with MMA (2 x 32KB, single acquire poll)
// + tight-spin acquire, redundant trailing barrier removed.
// ---------------------------------------------------------------------------
#define KSL        256
#define RPW        528
#define W_BYTES    (256 * RPW)             // 135168
#define H_OFF      W_BYTES                 // h staging: 128 rows x RPW = 67584
#define SMHV_OFF   (H_OFF + 32768)         // 2KB, inside h region (time-disjoint)
#define OWN_OFF    (H_OFF + 40960)         // 8KB own-quarter, inside h region
#define REMOTE_OFF (H_OFF + 128 * RPW)     // 202752, dedicated 3x8KB
#define REC_SMEM   (REMOTE_OFF + 3 * 8192) // 227328

__global__ __launch_bounds__(256, 1) __cluster_dims__(4, 1, 1)
void lstm_mma_kernel(
    const float* __restrict__ W,   // W_hh [4096,1024] fp32
    float* __restrict__ out,       // fp32 out (nullptr -> emit bf16 A hi/lo)
    float* __restrict__ hn,
    float* __restrict__ cn)
{
    extern __shared__ char sm[];
    const uint32_t smW = smem_u32(sm);
    const uint32_t smH = smW + H_OFF;
    float* ownb  = reinterpret_cast<float*>(sm + OWN_OFF);
    float* rems  = reinterpret_cast<float*>(sm + REMOTE_OFF);
    float* smHv  = reinterpret_cast<float*>(sm + SMHV_OFF);

    const int tid = threadIdx.x;
    const int wid = tid >> 5;
    const int lane = tid & 31;
    const int grp = blockIdx.x >> 2;     // 0..31
    const int r   = blockIdx.x & 3;      // k-slice == cluster rank
    const int wr  = wid & 3;             // warp row group (= destination rank)
    const int wc  = wid >> 2;            // warp col group

    // ---- Stage W_hh slice into SMEM (hi/lo), rows = u*4 + gate ----
    {
        const int row = tid >> 1;
        const int half = tid & 1;
        const int u = row >> 2, gg = row & 3;
        const float* src = W + ((size_t)(gg * HID + grp * 32 + u)) * HID + r * KSL
                         + half * 128;
        __nv_bfloat16* dh = reinterpret_cast<__nv_bfloat16*>(sm + row * RPW) + half * 128;
        __nv_bfloat16* dl = reinterpret_cast<__nv_bfloat16*>(sm + (128 + row) * RPW) + half * 128;
        for (int k = 0; k < 128; k++) {
            float v = src[k];
            __nv_bfloat16 h = __float2bfloat16_rn(v);
            dh[k] = h;
            dl[k] = __float2bfloat16_rn(v - __bfloat162float(h));
        }
    }
    __syncthreads();
    CLUSTER_ARRIVE();   // epoch A0: slots free for step 0

    const int bq = tid & 63;
    const int uq = tid >> 6;
    float cst[2] = {0.f, 0.f};

    // precompute remote destination (only used when wr != r)
    const int ridx = (r < wr) ? r : r - 1;   // my slot index in receiver wr
    const uint32_t rem_dst = mapa_rank(smW + REMOTE_OFF + (uint32_t)(ridx * 8192), wr);

    for (int s = 0; s < SEQ; s++) {
        const int cb = s % 3;
        const int nb3 = (s + 1) % 3;

        // ---- Prefetch x-projection (independent of h) ----
        float pv[2][4];
#pragma unroll
        for (int p = 0; p < 2; p++) {
            const int u_local = r * 8 + uq + p * 4;
            const int j = grp * 32 + u_local;
            const float* pp = g_proj + ((size_t)(s * BATCH + bq)) * G4 + j;
#pragma unroll
            for (int gg = 0; gg < 4; gg++)
                pv[p][gg] = __ldg(&pp[gg * HID]);
        }

        // ---- Wait for the 8 source groups' h of step s-1 (acquire, tight) ----
        if (s > 0) {
            if (tid < 8) {
                const unsigned tgt = 4u * (unsigned)s;
                const unsigned* ad = &g_done[8 * r + tid];
                unsigned v;
                for (;;) {
                    asm volatile("ld.acquire.gpu.global.u32 %0, [%1];"
                                 : "=r"(v) : "l"(ad));
                    if (v >= tgt) break;
                }
            }
            __syncthreads();
        }

        // ---- Stage h slice in 2 chunks of 128 k-cols (32KB each) ----
#pragma unroll
        for (int c = 0; c < 2; c++) {
#pragma unroll
            for (int t = 0; t < 8; t++) {
                const int idx = tid + t * 256;       // 0..2047
                const int arr = idx >> 10;           // 0=hi 1=lo
                const int rem = idx & 1023;
                const int row = rem >> 4;            // batch row
                const int kc = c * 16 + (rem & 15);  // 16B chunk
                const __nv_bfloat16* g =
                    (arr ? g_hl[cb] : g_hh[cb]) + row * HID + r * KSL + kc * 8;
                CP_ASYNC16(smH + arr * (64 * RPW) + row * RPW + kc * 16, g);
            }
            CP_COMMIT();
        }

        // ---- MMA: C[128,64] partial over k-slice, bf16x3, chunk-pipelined ----
        float acc[2][4][4];
#pragma unroll
        for (int mt = 0; mt < 2; mt++)
#pragma unroll
            for (int nt = 0; nt < 4; nt++)
#pragma unroll
                for (int c = 0; c < 4; c++) acc[mt][nt][c] = 0.f;

        CP_WAIT1();          // chunk 0 landed
        __syncthreads();

#pragma unroll
        for (int half = 0; half < 2; half++) {
            if (half == 1) {
                CP_WAIT0();  // chunk 1 landed
                __syncthreads();
            }
#pragma unroll
            for (int k8 = 0; k8 < 8; k8++) {
                const int kk = half * 8 + k8;
                const uint32_t aoff = (lane & 15) * RPW + (lane >> 4) * 16 + kk * 32;
                const uint32_t boff = (lane & 7) * RPW + ((lane >> 3) & 1) * 16 + kk * 32;

                uint32_t awh[2][4], awl[2][4];
#pragma unroll
                for (int mt = 0; mt < 2; mt++) {
                    const uint32_t ar = (wr * 32 + mt * 16) * RPW;
                    ldsm4(awh[mt], smW + ar + aoff);
                    ldsm4(awl[mt], smW + 128 * RPW + ar + aoff);
                }
                uint32_t bh[4][2], bl[4][2];
#pragma unroll
                for (int nt = 0; nt < 4; nt++) {
                    const uint32_t br = (wc * 32 + nt * 8) * RPW;
                    ldsm2(bh[nt], smH + br + boff);
                    ldsm2(bl[nt], smH + 64 * RPW + br + boff);
                }
#pragma unroll
                for (int mt = 0; mt < 2; mt++)
#pragma unroll
                    for (int nt = 0; nt < 4; nt++) {
                        mma16816(acc[mt][nt], awh[mt], bh[nt]);
                        mma16816(acc[mt][nt], awh[mt], bl[nt]);
                        mma16816(acc[mt][nt], awl[mt], bh[nt]);
                    }
            }
        }

        // ---- all warps done reading h staging before ownb (aliased) write ----
        __syncthreads();

        // ---- Wait epoch A: all ranks' slots free (normally already done) ----
        CLUSTER_WAIT();

        // ---- Exchange: rows [wr*32, wr*32+32) go to rank wr ----
        if (wr == r) {
#pragma unroll
            for (int mt = 0; mt < 2; mt++) {
                const int rl = mt * 16 + (lane >> 2);
#pragma unroll
                for (int nt = 0; nt < 4; nt++) {
                    const int col = wc * 32 + nt * 8 + (lane & 3) * 2;
                    *reinterpret_cast<float2*>(&ownb[rl * 64 + col]) =
                        make_float2(acc[mt][nt][0], acc[mt][nt][1]);
                    *reinterpret_cast<float2*>(&ownb[(rl + 8) * 64 + col]) =
                        make_float2(acc[mt][nt][2], acc[mt][nt][3]);
                }
            }
        } else {
#pragma unroll
            for (int mt = 0; mt < 2; mt++) {
                const int rl = mt * 16 + (lane >> 2);
#pragma unroll
                for (int nt = 0; nt < 4; nt++) {
                    const int col = wc * 32 + nt * 8 + (lane & 3) * 2;
                    sts_cluster64(rem_dst + (uint32_t)(rl * 256 + col * 4),
                                  acc[mt][nt][0], acc[mt][nt][1]);
                    sts_cluster64(rem_dst + (uint32_t)((rl + 8) * 256 + col * 4),
                                  acc[mt][nt][2], acc[mt][nt][3]);
                }
            }
        }

        // ---- Epoch B rendezvous: all partials landed ----
        CLUSTER_ARRIVE();
        CLUSTER_WAIT();

        // ---- Reduce (own local + 3 remote slots) + elementwise ----
#pragma unroll
        for (int p = 0; p < 2; p++) {
            const int u_idx = uq + p * 4;
            const int u_local = r * 8 + u_idx;
            const int j = grp * 32 + u_local;
            float gate[4];
#pragma unroll
            for (int gg = 0; gg < 4; gg++) {
                const int off = (u_idx * 4 + gg) * 64 + bq;
                float t = ownb[off];
                t += rems[off];
                t += rems[2048 + off];
                t += rems[4096 + off];
                gate[gg] = t + pv[p][gg];
            }
            const float gi = sigmoidf_(gate[0]);
            const float gf = sigmoidf_(gate[1]);
            const float gG = tanhf_(gate[2]);
            const float go = sigmoidf_(gate[3]);
            const float cnew = gf * cst[p] + gi * gG;
            cst[p] = cnew;
            const float hv = go * tanhf_(cnew);
            smHv[u_idx * 64 + bq] = hv;
            if (s == SEQ - 1) {
                hn[bq * HID + j] = hv;
                cn[bq * HID + j] = cnew;
            }
        }
        __syncthreads();
        CLUSTER_ARRIVE();   // epoch A(s+1): my slots consumed / free

        // ---- h hi/lo stores FIRST (roles 0,1), then publish, then out ----
        const int j0 = grp * 32 + r * 8;
        const int role = tid >> 6;
        const int b = tid & 63;
        float hv8[8];
#pragma unroll
        for (int u = 0; u < 8; u++) hv8[u] = smHv[u * 64 + b];

        if (role == 0) {
            __nv_bfloat16 h8[8];
#pragma unroll
            for (int u = 0; u < 8; u++) h8[u] = __float2bfloat16_rn(hv8[u]);
            *reinterpret_cast<uint4*>(&g_hh[nb3][b * HID + j0]) =
                *reinterpret_cast<uint4*>(h8);
        } else if (role == 1) {
            __nv_bfloat16 l8[8];
#pragma unroll
            for (int u = 0; u < 8; u++) {
                __nv_bfloat16 h = __float2bfloat16_rn(hv8[u]);
                l8[u] = __float2bfloat16_rn(hv8[u] - __bfloat162float(h));
            }
            *reinterpret_cast<uint4*>(&g_hl[nb3][b * HID + j0]) =
                *reinterpret_cast<uint4*>(l8);
        }
        __syncthreads();

        // ---- Release publish: group counter (h is visible) ----
        if (tid == 0)
            asm volatile("red.release.gpu.global.add.u32 [%0], %1;"
                         :: "l"(&g_done[grp]), "r"(1u) : "memory");

        // ---- Layer output writes (off the inter-group critical path).
        //      No trailing barrier: next step's post-poll __syncthreads
        //      orders these reads of smHv before any new staging writes. ----
        if (role == 2) {
            if (out) {
                float* o = &out[((size_t)(s * BATCH + b)) * HID + j0];
                *reinterpret_cast<float4*>(o) =
                    make_float4(hv8[0], hv8[1], hv8[2], hv8[3]);
                *reinterpret_cast<float4*>(o + 4) =
                    make_float4(hv8[4], hv8[5], hv8[6], hv8[7]);
            } else {
                __nv_bfloat16 h8[8];
#pragma unroll
                for (int u = 0; u < 8; u++) h8[u] = __float2bfloat16_rn(hv8[u]);
                *reinterpret_cast<uint4*>(
                    &g_Ahi[((size_t)(s * BATCH + b)) * HID + j0]) =
                    *reinterpret_cast<uint4*>(h8);
            }
        } else if (role == 3) {
            if (!out) {
                __nv_bfloat16 l8[8];
#pragma unroll
                for (int u = 0; u < 8; u++) {
                    __nv_bfloat16 h = __float2bfloat16_rn(hv8[u]);
                    l8[u] = __float2bfloat16_rn(hv8[u] - __bfloat162float(h));
                }
                *reinterpret_cast<uint4*>(
                    &g_Alo[((size_t)(s * BATCH + b)) * HID + j0]) =
                    *reinterpret_cast<uint4*>(l8);
            }
        }
    }
    // match the final epoch-A arrive before exiting the cluster
    CLUSTER_WAIT();
}

// ---------------------------------------------------------------------------
// Launch
// ---------------------------------------------------------------------------
extern "C" void kernel_launch(void* const* d_in, const int* in_sizes, int n_in,
                              void* d_out, int out_size)
{
    const float* x     = (const float*)d_in[0];
    const float* Wih0  = (const float*)d_in[1];
    const float* Whh0  = (const float*)d_in[2];
    const float* bih0  = (const float*)d_in[3];
    const float* bhh0  = (const float*)d_in[4];
    const float* Wih1  = (const float*)d_in[5];
    const float* Whh1  = (const float*)d_in[6];
    const float* bih1  = (const float*)d_in[7];
    const float* bhh1  = (const float*)d_in[8];

    float* out1 = (float*)d_out;
    float* hn   = out1 + (size_t)SEQ * BATCH * HID;
    float* cn   = hn + 2 * BATCH * HID;

    cudaFuncSetAttribute(mma_gemm_kernel,
                         cudaFuncAttributeMaxDynamicSharedMemorySize, GEMM_SMEM);
    cudaFuncSetAttribute(lstm_mma_kernel,
                         cudaFuncAttributeMaxDynamicSharedMemorySize, REC_SMEM);

    __nv_bfloat16 *Ahi, *Alo, *Whi, *Wlo;
    cudaGetSymbolAddress((void**)&Ahi, g_Ahi);
    cudaGetSymbolAddress((void**)&Alo, g_Alo);
    cudaGetSymbolAddress((void**)&Whi, g_Whi);
    cudaGetSymbolAddress((void**)&Wlo, g_Wlo);

    dim3 mgrid(MROWS / 128, G4 / 128);

    // ---- Layer 0 ----
    split_kernel<<<2048, 256>>>(x, Ahi, Alo, (MROWS * HID) / 4);
    split_kernel<<<512, 256>>>(Wih0, Whi, Wlo, (G4 * HID) / 4);
    zero_state_kernel<<<64, 256>>>();
    mma_gemm_kernel<<<mgrid, 256, GEMM_SMEM>>>(bih0, bhh0);
    lstm_mma_kernel<<<128, 256, REC_SMEM>>>(Whh0, nullptr, hn, cn);

    // ---- Layer 1 ----
    split_kernel<<<512, 256>>>(Wih1, Whi, Wlo, (G4 * HID) / 4);
    zero_state_kernel<<<64, 256>>>();
    mma_gemm_kernel<<<mgrid, 256, GEMM_SMEM>>>(bih1, bhh1);
    lstm_mma_kernel<<<128, 256, REC_SMEM>>>(Whh1, out1,
                                            hn + BATCH * HID,
                                            cn + BATCH * HID);
}

// round 14
// speedup vs baseline: 1.0069x; 1.0069x over previous
#include <cuda_runtime.h>
#include <cuda_bf16.h>
#include <cstdint>

typedef unsigned long long u64;

// ---------------------------------------------------------------------------
// Problem constants
// ---------------------------------------------------------------------------
#define SEQ   512
#define BATCH 64
#define HID   1024
#define G4    4096
#define MROWS (SEQ * BATCH)   // 32768

// ---------------------------------------------------------------------------
// Scratch (device globals)
// ---------------------------------------------------------------------------
__device__ float g_proj[(size_t)MROWS * G4];          // [T*B, 4H] x-projection
__device__ __align__(16) __nv_bfloat16 g_Ahi[(size_t)MROWS * HID];
__device__ __align__(16) __nv_bfloat16 g_Alo[(size_t)MROWS * HID];
__device__ __align__(16) __nv_bfloat16 g_Whi[(size_t)G4 * HID];
__device__ __align__(16) __nv_bfloat16 g_Wlo[(size_t)G4 * HID];
__device__ __align__(16) __nv_bfloat16 g_hh[3][BATCH * HID];   // h hi, [b][j]
__device__ __align__(16) __nv_bfloat16 g_hl[3][BATCH * HID];   // h lo, [b][j]
__device__ unsigned g_done[32];                                // per-group h publish

// ---------------------------------------------------------------------------
// Helpers
// ---------------------------------------------------------------------------
__device__ __forceinline__ uint32_t smem_u32(const void* p) {
    uint32_t a;
    asm("{ .reg .u64 t; cvta.to.shared.u64 t, %1; cvt.u32.u64 %0, t; }"
        : "=r"(a) : "l"(p));
    return a;
}
__device__ __forceinline__ void ldsm4(uint32_t* r, uint32_t addr) {
    asm volatile("ldmatrix.sync.aligned.m8n8.x4.shared.b16 {%0,%1,%2,%3}, [%4];"
                 : "=r"(r[0]), "=r"(r[1]), "=r"(r[2]), "=r"(r[3]) : "r"(addr));
}
__device__ __forceinline__ void mma16816(float* c, const uint32_t* a, const uint32_t* b) {
    asm volatile("mma.sync.aligned.m16n8k16.row.col.f32.bf16.bf16.f32 "
                 "{%0,%1,%2,%3}, {%4,%5,%6,%7}, {%8,%9}, {%0,%1,%2,%3};"
                 : "+f"(c[0]), "+f"(c[1]), "+f"(c[2]), "+f"(c[3])
                 : "r"(a[0]), "r"(a[1]), "r"(a[2]), "r"(a[3]),
                   "r"(b[0]), "r"(b[1]));
}
#define CP_ASYNC16(sdst, gsrc) \
    asm volatile("cp.async.cg.shared.global [%0], [%1], 16;" :: "r"(sdst), "l"(gsrc))
#define CP_COMMIT() asm volatile("cp.async.commit_group;" ::: "memory")
#define CP_WAIT0()  asm volatile("cp.async.wait_group 0;" ::: "memory")
#define CP_WAIT1()  asm volatile("cp.async.wait_group 1;" ::: "memory")

#define CLUSTER_ARRIVE() asm volatile("barrier.cluster.arrive.aligned;" ::: "memory")
#define CLUSTER_WAIT()   asm volatile("barrier.cluster.wait.aligned;" ::: "memory")

__device__ __forceinline__ uint32_t mapa_rank(uint32_t addr, int rank) {
    uint32_t r;
    asm("mapa.shared::cluster.u32 %0, %1, %2;" : "=r"(r) : "r"(addr), "r"(rank));
    return r;
}
__device__ __forceinline__ void sts_cluster64(uint32_t addr, float a, float b) {
    u64 v; asm("mov.b64 %0, {%1,%2};" : "=l"(v) : "f"(a), "f"(b));
    asm volatile("st.shared::cluster.b64 [%0], %1;" :: "r"(addr), "l"(v) : "memory");
}

__device__ __forceinline__ float sigmoidf_(float x) { return 1.0f / (1.0f + __expf(-x)); }
__device__ __forceinline__ float tanhf_(float x) { return 2.0f / (1.0f + __expf(-2.0f * x)) - 1.0f; }

// ---------------------------------------------------------------------------
// Zero h buffer 0 + counters
// ---------------------------------------------------------------------------
__global__ void zero_state_kernel() {
    int i = blockIdx.x * blockDim.x + threadIdx.x;
    if (i < 32) g_done[i] = 0u;
    const uint4 z = make_uint4(0, 0, 0, 0);
    if (i < (BATCH * HID * 2) / 16) {
        reinterpret_cast<uint4*>(&g_hh[0][0])[i] = z;
        reinterpret_cast<uint4*>(&g_hl[0][0])[i] = z;
    }
}

// ---------------------------------------------------------------------------
// fp32 -> bf16 hi/lo split
// ---------------------------------------------------------------------------
__global__ void split_kernel(const float* __restrict__ src,
                             __nv_bfloat16* __restrict__ hi,
                             __nv_bfloat16* __restrict__ lo, int n4) {
    int i = blockIdx.x * blockDim.x + threadIdx.x;
    int stride = gridDim.x * blockDim.x;
    for (; i < n4; i += stride) {
        float4 v = reinterpret_cast<const float4*>(src)[i];
        __nv_bfloat16 h[4], l[4];
        float vv[4] = {v.x, v.y, v.z, v.w};
#pragma unroll
        for (int k = 0; k < 4; k++) {
            h[k] = __float2bfloat16_rn(vv[k]);
            l[k] = __float2bfloat16_rn(vv[k] - __bfloat162float(h[k]));
        }
        reinterpret_cast<uint2*>(hi)[i] = *reinterpret_cast<uint2*>(h);
        reinterpret_cast<uint2*>(lo)[i] = *reinterpret_cast<uint2*>(l);
    }
}

// ---------------------------------------------------------------------------
// bf16x3 GEMM via mma.sync — 256 threads, 8 warps (4m x 2n), 2-stage
// cp.async ring, 80KB SMEM -> 2 CTAs/SM.  W fragments loaded as paired
// ldsm4 (2 n-groups per instruction): per kk 12 LDSM vs 20.
// ---------------------------------------------------------------------------
#define KSTG       32
#define NSTAGES    (HID / KSTG)
#define PITCH_B    80
#define REG_BYTES  (128 * PITCH_B)
#define STG_BYTES  (4 * REG_BYTES)       // 40960
#define GEMM_SMEM  (2 * STG_BYTES)       // 81920 -> 2 CTAs/SM

__device__ __forceinline__ void stage_load(uint32_t sbase, int s, int m0, int n0,
                                           int tid) {
    const int kt = s * KSTG;
    const uint32_t dst = sbase + (s & 1) * STG_BYTES;
#pragma unroll
    for (int r = 0; r < 4; r++) {
        const __nv_bfloat16* src =
            (r == 0) ? g_Ahi : (r == 1) ? g_Alo : (r == 2) ? g_Whi : g_Wlo;
        const int rb = (r < 2) ? m0 : n0;
#pragma unroll
        for (int j = 0; j < 2; j++) {
            const int chunk = tid + j * 256;
            const int row = chunk >> 2;
            const int kc = chunk & 3;
            const void* g = src + (size_t)(rb + row) * HID + kt + kc * 8;
            const uint32_t sd = dst + r * REG_BYTES + row * PITCH_B + kc * 16;
            CP_ASYNC16(sd, g);
        }
    }
}

__global__ __launch_bounds__(256, 2) void mma_gemm_kernel(
    const float* __restrict__ bias1, const float* __restrict__ bias2)
{
    extern __shared__ char dsm[];
    __shared__ float s_bias[128];

    const int tid = threadIdx.x;
    const int wid = tid >> 5;
    const int lane = tid & 31;
    const int m0 = blockIdx.x * 128;
    const int n0 = blockIdx.y * 128;
    const int wm = (wid & 3) * 32;
    const int wn = (wid >> 2) * 64;

    const uint32_t sbase = smem_u32(dsm);

    if (tid < 128) s_bias[tid] = bias1[n0 + tid] + bias2[n0 + tid];

    float acc[2][8][4];
#pragma unroll
    for (int ma = 0; ma < 2; ma++)
#pragma unroll
        for (int nb = 0; nb < 8; nb++)
#pragma unroll
            for (int c = 0; c < 4; c++) acc[ma][nb][c] = 0.f;

    stage_load(sbase, 0, m0, n0, tid);
    CP_COMMIT();

    for (int s = 0; s < NSTAGES; s++) {
        if (s + 1 < NSTAGES) stage_load(sbase, s + 1, m0, n0, tid);
        CP_COMMIT();
        CP_WAIT1();
        __syncthreads();

        const uint32_t sb = sbase + (s & 1) * STG_BYTES;
        const uint32_t aHi = sb;
        const uint32_t aLo = sb + REG_BYTES;
        const uint32_t wHi = sb + 2 * REG_BYTES;
        const uint32_t wLo = sb + 3 * REG_BYTES;

#pragma unroll
        for (int kk = 0; kk < 2; kk++) {
            const uint32_t aoff = (lane & 15) * PITCH_B + (lane >> 4) * 16 + kk * 32;

            uint32_t ahi[2][4], alo[2][4];
            ldsm4(ahi[0], aHi + (wm + 0) * PITCH_B + aoff);
            ldsm4(ahi[1], aHi + (wm + 16) * PITCH_B + aoff);
            ldsm4(alo[0], aLo + (wm + 0) * PITCH_B + aoff);
            ldsm4(alo[1], aLo + (wm + 16) * PITCH_B + aoff);

            // paired B-fragment loads: matrices (nb0 k0-7, nb0 k8-15,
            // nb1 k0-7, nb1 k8-15) per x4
            uint32_t wh4[4][4], wl4[4][4];
#pragma unroll
            for (int p = 0; p < 4; p++) {
                const uint32_t wrow =
                    (uint32_t)(wn + p * 16 + ((lane >> 4) & 1) * 8 + (lane & 7)) * PITCH_B
                    + ((lane >> 3) & 1) * 16 + kk * 32;
                ldsm4(wh4[p], wHi + wrow);
                ldsm4(wl4[p], wLo + wrow);
            }

#pragma unroll
            for (int ma = 0; ma < 2; ma++)
#pragma unroll
                for (int nb = 0; nb < 8; nb++) {
                    const uint32_t* bh = &wh4[nb >> 1][(nb & 1) * 2];
                    const uint32_t* bl = &wl4[nb >> 1][(nb & 1) * 2];
                    mma16816(acc[ma][nb], ahi[ma], bh);
                    mma16816(acc[ma][nb], ahi[ma], bl);
                    mma16816(acc[ma][nb], alo[ma], bh);
                }
        }
        __syncthreads();
    }

#pragma unroll
    for (int ma = 0; ma < 2; ma++) {
        const int row = m0 + wm + ma * 16 + (lane >> 2);
#pragma unroll
        for (int nb = 0; nb < 8; nb++) {
            const int cloc = wn + nb * 8 + (lane & 3) * 2;
            const int col = n0 + cloc;
            const float b0 = s_bias[cloc], b1 = s_bias[cloc + 1];
            float2 v0 = make_float2(acc[ma][nb][0] + b0, acc[ma][nb][1] + b1);
            float2 v1 = make_float2(acc[ma][nb][2] + b0, acc[ma][nb][3] + b1);
            *reinterpret_cast<float2*>(&g_proj[(size_t)row * G4 + col]) = v0;
            *reinterpret_cast<float2*>(&g_proj[(size_t)(row + 8) * G4 + col]) = v1;
        }
    }
}

// ---------------------------------------------------------------------------
// Persistent LSTM recurrence — exact R12 structure (proven 14.27ms), with
// paired ldsm4 B-fragment loads in the MMA loop (8 LDSM/kk vs 12).
// ---------------------------------------------------------------------------
#define KSL        256
#define RPW        528
#define W_BYTES    (256 * RPW)             // 135168
#define H_OFF      W_BYTES                 // h staging: 128 rows x RPW
#define SMHV_OFF   (H_OFF + 32768)         // 2KB, inside h region (time-disjoint)
#define OWN_OFF    (H_OFF + 40960)         // 8KB own-quarter, inside h region
#define REMOTE_OFF (H_OFF + 128 * RPW)     // 202752, dedicated 3x8KB
#define REC_SMEM   (REMOTE_OFF + 3 * 8192) // 227328

__global__ __launch_bounds__(256, 1) __cluster_dims__(4, 1, 1)
void lstm_mma_kernel(
    const float* __restrict__ W,   // W_hh [4096,1024] fp32
    float* __restrict__ out,       // fp32 out (nullptr -> emit bf16 A hi/lo)
    float* __restrict__ hn,
    float* __restrict__ cn)
{
    extern __shared__ char sm[];
    const uint32_t smW = smem_u32(sm);
    const uint32_t smH = smW + H_OFF;
    float* ownb  = reinterpret_cast<float*>(sm + OWN_OFF);
    float* rems  = reinterpret_cast<float*>(sm + REMOTE_OFF);
    float* smHv  = reinterpret_cast<float*>(sm + SMHV_OFF);

    const int tid = threadIdx.x;
    const int wid = tid >> 5;
    const int lane = tid & 31;
    const int grp = blockIdx.x >> 2;     // 0..31
    const int r   = blockIdx.x & 3;      // k-slice == cluster rank
    const int wr  = wid & 3;             // warp row group (= destination rank)
    const int wc  = wid >> 2;            // warp col group

    // ---- Stage W_hh slice into SMEM (hi/lo), rows = u*4 + gate ----
    {
        const int row = tid >> 1;
        const int half = tid & 1;
        const int u = row >> 2, gg = row & 3;
        const float* src = W + ((size_t)(gg * HID + grp * 32 + u)) * HID + r * KSL
                         + half * 128;
        __nv_bfloat16* dh = reinterpret_cast<__nv_bfloat16*>(sm + row * RPW) + half * 128;
        __nv_bfloat16* dl = reinterpret_cast<__nv_bfloat16*>(sm + (128 + row) * RPW) + half * 128;
        for (int k = 0; k < 128; k++) {
            float v = src[k];
            __nv_bfloat16 h = __float2bfloat16_rn(v);
            dh[k] = h;
            dl[k] = __float2bfloat16_rn(v - __bfloat162float(h));
        }
    }
    __syncthreads();
    CLUSTER_ARRIVE();   // epoch A0: slots free for step 0

    const int bq = tid & 63;
    const int uq = tid >> 6;
    float cst[2] = {0.f, 0.f};

    // precompute remote destination (only used when wr != r)
    const int ridx = (r < wr) ? r : r - 1;   // my slot index in receiver wr
    const uint32_t rem_dst = mapa_rank(smW + REMOTE_OFF + (uint32_t)(ridx * 8192), wr);

    for (int s = 0; s < SEQ; s++) {
        const int cb = s % 3;
        const int nb3 = (s + 1) % 3;

        // ---- Prefetch x-projection (independent of h) ----
        float pv[2][4];
#pragma unroll
        for (int p = 0; p < 2; p++) {
            const int u_local = r * 8 + uq + p * 4;
            const int j = grp * 32 + u_local;
            const float* pp = g_proj + ((size_t)(s * BATCH + bq)) * G4 + j;
#pragma unroll
            for (int gg = 0; gg < 4; gg++)
                pv[p][gg] = __ldg(&pp[gg * HID]);
        }

        // ---- Wait for the 8 source groups' h of step s-1 (acquire) ----
        if (s > 0) {
            if (tid < 8) {
                const unsigned tgt = 4u * (unsigned)s;
                const unsigned* ad = &g_done[8 * r + tid];
                unsigned v;
                for (;;) {
                    asm volatile("ld.acquire.gpu.global.u32 %0, [%1];"
                                 : "=r"(v) : "l"(ad));
                    if (v >= tgt) break;
                    __nanosleep(32);
                }
            }
            __syncthreads();
        }

        // ---- Stage h slice (64 rows x 256 k, hi+lo) via cp.async ----
#pragma unroll
        for (int t = 0; t < 16; t++) {
            const int idx = tid + t * 256;       // 0..4095
            const int arr = idx >> 11;           // 0=hi 1=lo
            const int rem = idx & 2047;
            const int row = rem >> 5;            // batch row
            const int kc = rem & 31;             // 16B chunk
            const __nv_bfloat16* g =
                (arr ? g_hl[cb] : g_hh[cb]) + row * HID + r * KSL + kc * 8;
            CP_ASYNC16(smH + arr * (64 * RPW) + row * RPW + kc * 16, g);
        }
        CP_COMMIT();
        CP_WAIT0();
        __syncthreads();

        // ---- MMA: C[128,64] partial over k-slice, bf16x3 ----
        float acc[2][4][4];
#pragma unroll
        for (int mt = 0; mt < 2; mt++)
#pragma unroll
            for (int nt = 0; nt < 4; nt++)
#pragma unroll
                for (int c = 0; c < 4; c++) acc[mt][nt][c] = 0.f;

#pragma unroll
        for (int kk = 0; kk < 16; kk++) {
            const uint32_t aoff = (lane & 15) * RPW + (lane >> 4) * 16 + kk * 32;

            uint32_t awh[2][4], awl[2][4];
#pragma unroll
            for (int mt = 0; mt < 2; mt++) {
                const uint32_t ar = (wr * 32 + mt * 16) * RPW;
                ldsm4(awh[mt], smW + ar + aoff);
                ldsm4(awl[mt], smW + 128 * RPW + ar + aoff);
            }
            // paired B loads: 2 n-groups per ldsm4
            uint32_t bh4[2][4], bl4[2][4];
#pragma unroll
            for (int p = 0; p < 2; p++) {
                const uint32_t brow =
                    (uint32_t)(wc * 32 + p * 16 + ((lane >> 4) & 1) * 8 + (lane & 7)) * RPW
                    + ((lane >> 3) & 1) * 16 + kk * 32;
                ldsm4(bh4[p], smH + brow);
                ldsm4(bl4[p], smH + 64 * RPW + brow);
            }
#pragma unroll
            for (int mt = 0; mt < 2; mt++)
#pragma unroll
                for (int nt = 0; nt < 4; nt++) {
                    const uint32_t* bh = &bh4[nt >> 1][(nt & 1) * 2];
                    const uint32_t* bl = &bl4[nt >> 1][(nt & 1) * 2];
                    mma16816(acc[mt][nt], awh[mt], bh);
                    mma16816(acc[mt][nt], awh[mt], bl);
                    mma16816(acc[mt][nt], awl[mt], bh);
                }
        }

        // ---- all warps must finish reading h staging before ownb
        //      (which aliases it) is written ----
        __syncthreads();

        // ---- Wait epoch A: all ranks' slots free (normally already done) ----
        CLUSTER_WAIT();

        // ---- Exchange: rows [wr*32, wr*32+32) go to rank wr ----
        if (wr == r) {
            // own quarter: local stores, off the DSMEM port
#pragma unroll
            for (int mt = 0; mt < 2; mt++) {
                const int rl = mt * 16 + (lane >> 2);
#pragma unroll
                for (int nt = 0; nt < 4; nt++) {
                    const int col = wc * 32 + nt * 8 + (lane & 3) * 2;
                    *reinterpret_cast<float2*>(&ownb[rl * 64 + col]) =
                        make_float2(acc[mt][nt][0], acc[mt][nt][1]);
                    *reinterpret_cast<float2*>(&ownb[(rl + 8) * 64 + col]) =
                        make_float2(acc[mt][nt][2], acc[mt][nt][3]);
                }
            }
        } else {
#pragma unroll
            for (int mt = 0; mt < 2; mt++) {
                const int rl = mt * 16 + (lane >> 2);
#pragma unroll
                for (int nt = 0; nt < 4; nt++) {
                    const int col = wc * 32 + nt * 8 + (lane & 3) * 2;
                    sts_cluster64(rem_dst + (uint32_t)(rl * 256 + col * 4),
                                  acc[mt][nt][0], acc[mt][nt][1]);
                    sts_cluster64(rem_dst + (uint32_t)((rl + 8) * 256 + col * 4),
                                  acc[mt][nt][2], acc[mt][nt][3]);
                }
            }
        }

        // ---- Epoch B rendezvous: all partials landed ----
        CLUSTER_ARRIVE();
        CLUSTER_WAIT();

        // ---- Reduce (own local + 3 remote slots) + elementwise ----
#pragma unroll
        for (int p = 0; p < 2; p++) {
            const int u_idx = uq + p * 4;
            const int u_local = r * 8 + u_idx;
            const int j = grp * 32 + u_local;
            float gate[4];
#pragma unroll
            for (int gg = 0; gg < 4; gg++) {
                const int off = (u_idx * 4 + gg) * 64 + bq;
                float t = ownb[off];
                t += rems[off];
                t += rems[2048 + off];
                t += rems[4096 + off];
                gate[gg] = t + pv[p][gg];
            }
            const float gi = sigmoidf_(gate[0]);
            const float gf = sigmoidf_(gate[1]);
            const float gG = tanhf_(gate[2]);
            const float go = sigmoidf_(gate[3]);
            const float cnew = gf * cst[p] + gi * gG;
            cst[p] = cnew;
            const float hv = go * tanhf_(cnew);
            smHv[u_idx * 64 + bq] = hv;
            if (s == SEQ - 1) {
                hn[bq * HID + j] = hv;
                cn[bq * HID + j] = cnew;
            }
        }
        __syncthreads();
        CLUSTER_ARRIVE();   // epoch A(s+1): my slots consumed / free

        // ---- h hi/lo stores FIRST (roles 0,1), then publish, then out ----
        const int j0 = grp * 32 + r * 8;
        const int role = tid >> 6;
        const int b = tid & 63;
        float hv8[8];
#pragma unroll
        for (int u = 0; u < 8; u++) hv8[u] = smHv[u * 64 + b];

        if (role == 0) {
            __nv_bfloat16 h8[8];
#pragma unroll
            for (int u = 0; u < 8; u++) h8[u] = __float2bfloat16_rn(hv8[u]);
            *reinterpret_cast<uint4*>(&g_hh[nb3][b * HID + j0]) =
                *reinterpret_cast<uint4*>(h8);
        } else if (role == 1) {
            __nv_bfloat16 l8[8];
#pragma unroll
            for (int u = 0; u < 8; u++) {
                __nv_bfloat16 h = __float2bfloat16_rn(hv8[u]);
                l8[u] = __float2bfloat16_rn(hv8[u] - __bfloat162float(h));
            }
            *reinterpret_cast<uint4*>(&g_hl[nb3][b * HID + j0]) =
                *reinterpret_cast<uint4*>(l8);
        }
        __syncthreads();

        // ---- Release publish: group counter (h is visible) ----
        if (tid == 0)
            asm volatile("red.release.gpu.global.add.u32 [%0], %1;"
                         :: "l"(&g_done[grp]), "r"(1u) : "memory");

        // ---- Layer output writes (off the inter-group critical path) ----
        if (role == 2) {
            if (out) {
                float* o = &out[((size_t)(s * BATCH + b)) * HID + j0];
                *reinterpret_cast<float4*>(o) =
                    make_float4(hv8[0], hv8[1], hv8[2], hv8[3]);
                *reinterpret_cast<float4*>(o + 4) =
                    make_float4(hv8[4], hv8[5], hv8[6], hv8[7]);
            } else {
                __nv_bfloat16 h8[8];
#pragma unroll
                for (int u = 0; u < 8; u++) h8[u] = __float2bfloat16_rn(hv8[u]);
                *reinterpret_cast<uint4*>(
                    &g_Ahi[((size_t)(s * BATCH + b)) * HID + j0]) =
                    *reinterpret_cast<uint4*>(h8);
            }
        } else if (role == 3) {
            if (!out) {
                __nv_bfloat16 l8[8];
#pragma unroll
                for (int u = 0; u < 8; u++) {
                    __nv_bfloat16 h = __float2bfloat16_rn(hv8[u]);
                    l8[u] = __float2bfloat16_rn(hv8[u] - __bfloat162float(h));
                }
                *reinterpret_cast<uint4*>(
                    &g_Alo[((size_t)(s * BATCH + b)) * HID + j0]) =
                    *reinterpret_cast<uint4*>(l8);
            }
        }
        __syncthreads();
    }
    // match the final epoch-A arrive before exiting the cluster
    CLUSTER_WAIT();
}

// ---------------------------------------------------------------------------
// Launch
// ---------------------------------------------------------------------------
extern "C" void kernel_launch(void* const* d_in, const int* in_sizes, int n_in,
                              void* d_out, int out_size)
{
    const float* x     = (const float*)d_in[0];
    const float* Wih0  = (const float*)d_in[1];
    const float* Whh0  = (const float*)d_in[2];
    const float* bih0  = (const float*)d_in[3];
    const float* bhh0  = (const float*)d_in[4];
    const float* Wih1  = (const float*)d_in[5];
    const float* Whh1  = (const float*)d_in[6];
    const float* bih1  = (const float*)d_in[7];
    const float* bhh1  = (const float*)d_in[8];

    float* out1 = (float*)d_out;
    float* hn   = out1 + (size_t)SEQ * BATCH * HID;
    float* cn   = hn + 2 * BATCH * HID;

    cudaFuncSetAttribute(mma_gemm_kernel,
                         cudaFuncAttributeMaxDynamicSharedMemorySize, GEMM_SMEM);
    cudaFuncSetAttribute(lstm_mma_kernel,
                         cudaFuncAttributeMaxDynamicSharedMemorySize, REC_SMEM);

    __nv_bfloat16 *Ahi, *Alo, *Whi, *Wlo;
    cudaGetSymbolAddress((void**)&Ahi, g_Ahi);
    cudaGetSymbolAddress((void**)&Alo, g_Alo);
    cudaGetSymbolAddress((void**)&Whi, g_Whi);
    cudaGetSymbolAddress((void**)&Wlo, g_Wlo);

    dim3 mgrid(MROWS / 128, G4 / 128);

    // ---- Layer 0 ----
    split_kernel<<<2048, 256>>>(x, Ahi, Alo, (MROWS * HID) / 4);
    split_kernel<<<512, 256>>>(Wih0, Whi, Wlo, (G4 * HID) / 4);
    zero_state_kernel<<<64, 256>>>();
    mma_gemm_kernel<<<mgrid, 256, GEMM_SMEM>>>(bih0, bhh0);
    lstm_mma_kernel<<<128, 256, REC_SMEM>>>(Whh0, nullptr, hn, cn);

    // ---- Layer 1 ----
    split_kernel<<<512, 256>>>(Wih1, Whi, Wlo, (G4 * HID) / 4);
    zero_state_kernel<<<64, 256>>>();
    mma_gemm_kernel<<<mgrid, 256, GEMM_SMEM>>>(bih1, bhh1);
    lstm_mma_kernel<<<128, 256, REC_SMEM>>>(Whh1, out1,
                                            hn + BATCH * HID,
                                            cn + BATCH * HID);
}

// round 15
// speedup vs baseline: 1.0379x; 1.0307x over previous
#include <cuda_runtime.h>
#include <cuda_bf16.h>
#include <cstdint>

typedef unsigned long long u64;

// ---------------------------------------------------------------------------
// Problem constants
// ---------------------------------------------------------------------------
#define SEQ   512
#define BATCH 64
#define HID   1024
#define G4    4096
#define MROWS (SEQ * BATCH)   // 32768

// ---------------------------------------------------------------------------
// Scratch (device globals)
// ---------------------------------------------------------------------------
__device__ float g_proj[(size_t)MROWS * G4];          // [T*B, 4H] x-projection
__device__ __align__(16) __nv_bfloat16 g_Ahi[(size_t)MROWS * HID];
__device__ __align__(16) __nv_bfloat16 g_Alo[(size_t)MROWS * HID];
__device__ __align__(16) __nv_bfloat16 g_Whi[(size_t)G4 * HID];
__device__ __align__(16) __nv_bfloat16 g_Wlo[(size_t)G4 * HID];
__device__ __align__(16) __nv_bfloat16 g_hh[3][BATCH * HID];   // h hi, [b][j]
__device__ __align__(16) __nv_bfloat16 g_hl[3][BATCH * HID];   // h lo, [b][j]
__device__ unsigned g_done[32];                                // per-group h publish

// ---------------------------------------------------------------------------
// Helpers
// ---------------------------------------------------------------------------
__device__ __forceinline__ uint32_t smem_u32(const void* p) {
    uint32_t a;
    asm("{ .reg .u64 t; cvta.to.shared.u64 t, %1; cvt.u32.u64 %0, t; }"
        : "=r"(a) : "l"(p));
    return a;
}
__device__ __forceinline__ void ldsm4(uint32_t* r, uint32_t addr) {
    asm volatile("ldmatrix.sync.aligned.m8n8.x4.shared.b16 {%0,%1,%2,%3}, [%4];"
                 : "=r"(r[0]), "=r"(r[1]), "=r"(r[2]), "=r"(r[3]) : "r"(addr));
}
__device__ __forceinline__ void mma16816(float* c, const uint32_t* a, const uint32_t* b) {
    asm volatile("mma.sync.aligned.m16n8k16.row.col.f32.bf16.bf16.f32 "
                 "{%0,%1,%2,%3}, {%4,%5,%6,%7}, {%8,%9}, {%0,%1,%2,%3};"
                 : "+f"(c[0]), "+f"(c[1]), "+f"(c[2]), "+f"(c[3])
                 : "r"(a[0]), "r"(a[1]), "r"(a[2]), "r"(a[3]),
                   "r"(b[0]), "r"(b[1]));
}
#define CP_ASYNC16(sdst, gsrc) \
    asm volatile("cp.async.cg.shared.global [%0], [%1], 16;" :: "r"(sdst), "l"(gsrc))
#define CP_COMMIT() asm volatile("cp.async.commit_group;" ::: "memory")
#define CP_WAIT0()  asm volatile("cp.async.wait_group 0;" ::: "memory")
#define CP_WAIT1()  asm volatile("cp.async.wait_group 1;" ::: "memory")

#define CLUSTER_SYNC() do { \
    asm volatile("barrier.cluster.arrive.aligned;" ::: "memory"); \
    asm volatile("barrier.cluster.wait.aligned;" ::: "memory"); \
} while (0)

__device__ __forceinline__ uint32_t mapa_rank(uint32_t addr, int rank) {
    uint32_t r;
    asm("mapa.shared::cluster.u32 %0, %1, %2;" : "=r"(r) : "r"(addr), "r"(rank));
    return r;
}

#define MBAR_INIT(addr, cnt) \
    asm volatile("mbarrier.init.shared.b64 [%0], %1;" :: "r"(addr), "r"(cnt) : "memory")
#define MBAR_EXPECT_TX(addr, tx) \
    asm volatile("mbarrier.arrive.expect_tx.shared.b64 _, [%0], %1;" \
                 :: "r"(addr), "r"(tx) : "memory")
#define MBAR_ARRIVE_REMOTE(addr) \
    asm volatile("mbarrier.arrive.shared::cluster.b64 _, [%0];" :: "r"(addr) : "memory")
#define MBAR_WAIT(addr, par) do {                                              \
    uint32_t _m = (addr), _p = (par), _d;                                      \
    asm volatile("{\n\t.reg .pred p;\n\t"                                      \
        "mbarrier.try_wait.parity.acquire.cta.shared::cta.b64 p, [%1], %2;\n\t"\
        "selp.b32 %0, 1, 0, p;\n\t}" : "=r"(_d) : "r"(_m), "r"(_p) : "memory");\
    if (!_d) {                                                                 \
        asm volatile("{\n\t.reg .pred P1;\n\tWL_%=:\n\t"                       \
            "mbarrier.try_wait.parity.acquire.cta.shared::cta.b64 P1, [%0], %1, 0x989680;\n\t" \
            "@P1 bra.uni WD_%=;\n\tbra.uni WL_%=;\n\tWD_%=:\n\t}"              \
            :: "r"(_m), "r"(_p) : "memory");                                   \
    } } while (0)

// remote store with tx-completion on receiver's mbarrier
__device__ __forceinline__ void st_async64(uint32_t addr, float a, float b,
                                           uint32_t rbar) {
    u64 v; asm("mov.b64 %0, {%1,%2};" : "=l"(v) : "f"(a), "f"(b));
    asm volatile(
        "st.async.weak.shared::cluster.mbarrier::complete_tx::bytes.b64 [%0], %1, [%2];"
        :: "r"(addr), "l"(v), "r"(rbar) : "memory");
}

__device__ __forceinline__ float sigmoidf_(float x) { return 1.0f / (1.0f + __expf(-x)); }
__device__ __forceinline__ float tanhf_(float x) { return 2.0f / (1.0f + __expf(-2.0f * x)) - 1.0f; }

// ---------------------------------------------------------------------------
// Zero h buffer 0 + counters
// ---------------------------------------------------------------------------
__global__ void zero_state_kernel() {
    int i = blockIdx.x * blockDim.x + threadIdx.x;
    if (i < 32) g_done[i] = 0u;
    const uint4 z = make_uint4(0, 0, 0, 0);
    if (i < (BATCH * HID * 2) / 16) {
        reinterpret_cast<uint4*>(&g_hh[0][0])[i] = z;
        reinterpret_cast<uint4*>(&g_hl[0][0])[i] = z;
    }
}

// ---------------------------------------------------------------------------
// fp32 -> bf16 hi/lo split
// ---------------------------------------------------------------------------
__global__ void split_kernel(const float* __restrict__ src,
                             __nv_bfloat16* __restrict__ hi,
                             __nv_bfloat16* __restrict__ lo, int n4) {
    int i = blockIdx.x * blockDim.x + threadIdx.x;
    int stride = gridDim.x * blockDim.x;
    for (; i < n4; i += stride) {
        float4 v = reinterpret_cast<const float4*>(src)[i];
        __nv_bfloat16 h[4], l[4];
        float vv[4] = {v.x, v.y, v.z, v.w};
#pragma unroll
        for (int k = 0; k < 4; k++) {
            h[k] = __float2bfloat16_rn(vv[k]);
            l[k] = __float2bfloat16_rn(vv[k] - __bfloat162float(h[k]));
        }
        reinterpret_cast<uint2*>(hi)[i] = *reinterpret_cast<uint2*>(h);
        reinterpret_cast<uint2*>(lo)[i] = *reinterpret_cast<uint2*>(l);
    }
}

// ---------------------------------------------------------------------------
// bf16x3 GEMM via mma.sync — R14 version (proven): 256 threads, 8 warps,
// 2-stage cp.async ring, paired ldsm4 W loads, 2 CTAs/SM.
// ---------------------------------------------------------------------------
#define KSTG       32
#define NSTAGES    (HID / KSTG)
#define PITCH_B    80
#define REG_BYTES  (128 * PITCH_B)
#define STG_BYTES  (4 * REG_BYTES)       // 40960
#define GEMM_SMEM  (2 * STG_BYTES)       // 81920 -> 2 CTAs/SM

__device__ __forceinline__ void stage_load(uint32_t sbase, int s, int m0, int n0,
                                           int tid) {
    const int kt = s * KSTG;
    const uint32_t dst = sbase + (s & 1) * STG_BYTES;
#pragma unroll
    for (int r = 0; r < 4; r++) {
        const __nv_bfloat16* src =
            (r == 0) ? g_Ahi : (r == 1) ? g_Alo : (r == 2) ? g_Whi : g_Wlo;
        const int rb = (r < 2) ? m0 : n0;
#pragma unroll
        for (int j = 0; j < 2; j++) {
            const int chunk = tid + j * 256;
            const int row = chunk >> 2;
            const int kc = chunk & 3;
            const void* g = src + (size_t)(rb + row) * HID + kt + kc * 8;
            const uint32_t sd = dst + r * REG_BYTES + row * PITCH_B + kc * 16;
            CP_ASYNC16(sd, g);
        }
    }
}

__global__ __launch_bounds__(256, 2) void mma_gemm_kernel(
    const float* __restrict__ bias1, const float* __restrict__ bias2)
{
    extern __shared__ char dsm[];
    __shared__ float s_bias[128];

    const int tid = threadIdx.x;
    const int wid = tid >> 5;
    const int lane = tid & 31;
    const int m0 = blockIdx.x * 128;
    const int n0 = blockIdx.y * 128;
    const int wm = (wid & 3) * 32;
    const int wn = (wid >> 2) * 64;

    const uint32_t sbase = smem_u32(dsm);

    if (tid < 128) s_bias[tid] = bias1[n0 + tid] + bias2[n0 + tid];

    float acc[2][8][4];
#pragma unroll
    for (int ma = 0; ma < 2; ma++)
#pragma unroll
        for (int nb = 0; nb < 8; nb++)
#pragma unroll
            for (int c = 0; c < 4; c++) acc[ma][nb][c] = 0.f;

    stage_load(sbase, 0, m0, n0, tid);
    CP_COMMIT();

    for (int s = 0; s < NSTAGES; s++) {
        if (s + 1 < NSTAGES) stage_load(sbase, s + 1, m0, n0, tid);
        CP_COMMIT();
        CP_WAIT1();
        __syncthreads();

        const uint32_t sb = sbase + (s & 1) * STG_BYTES;
        const uint32_t aHi = sb;
        const uint32_t aLo = sb + REG_BYTES;
        const uint32_t wHi = sb + 2 * REG_BYTES;
        const uint32_t wLo = sb + 3 * REG_BYTES;

#pragma unroll
        for (int kk = 0; kk < 2; kk++) {
            const uint32_t aoff = (lane & 15) * PITCH_B + (lane >> 4) * 16 + kk * 32;

            uint32_t ahi[2][4], alo[2][4];
            ldsm4(ahi[0], aHi + (wm + 0) * PITCH_B + aoff);
            ldsm4(ahi[1], aHi + (wm + 16) * PITCH_B + aoff);
            ldsm4(alo[0], aLo + (wm + 0) * PITCH_B + aoff);
            ldsm4(alo[1], aLo + (wm + 16) * PITCH_B + aoff);

            uint32_t wh4[4][4], wl4[4][4];
#pragma unroll
            for (int p = 0; p < 4; p++) {
                const uint32_t wrow =
                    (uint32_t)(wn + p * 16 + ((lane >> 4) & 1) * 8 + (lane & 7)) * PITCH_B
                    + ((lane >> 3) & 1) * 16 + kk * 32;
                ldsm4(wh4[p], wHi + wrow);
                ldsm4(wl4[p], wLo + wrow);
            }

#pragma unroll
            for (int ma = 0; ma < 2; ma++)
#pragma unroll
                for (int nb = 0; nb < 8; nb++) {
                    const uint32_t* bh = &wh4[nb >> 1][(nb & 1) * 2];
                    const uint32_t* bl = &wl4[nb >> 1][(nb & 1) * 2];
                    mma16816(acc[ma][nb], ahi[ma], bh);
                    mma16816(acc[ma][nb], ahi[ma], bl);
                    mma16816(acc[ma][nb], alo[ma], bh);
                }
        }
        __syncthreads();
    }

#pragma unroll
    for (int ma = 0; ma < 2; ma++) {
        const int row = m0 + wm + ma * 16 + (lane >> 2);
#pragma unroll
        for (int nb = 0; nb < 8; nb++) {
            const int cloc = wn + nb * 8 + (lane & 3) * 2;
            const int col = n0 + cloc;
            const float b0 = s_bias[cloc], b1 = s_bias[cloc + 1];
            float2 v0 = make_float2(acc[ma][nb][0] + b0, acc[ma][nb][1] + b1);
            float2 v1 = make_float2(acc[ma][nb][2] + b0, acc[ma][nb][3] + b1);
            *reinterpret_cast<float2*>(&g_proj[(size_t)row * G4 + col]) = v0;
            *reinterpret_cast<float2*>(&g_proj[(size_t)(row + 8) * G4 + col]) = v1;
        }
    }
}

// ---------------------------------------------------------------------------
// Persistent LSTM recurrence — R14 structure with the two per-step cluster
// rendezvous replaced by point-to-point mbarriers:
//   full: tx-count (3 x 8192 B of st.async partials per step)
//   free: count-3 (each receiver arrives after consuming my partials)
// ---------------------------------------------------------------------------
#define KSL        256
#define RPW        528
#define W_BYTES    (256 * RPW)             // 135168
#define H_OFF      W_BYTES                 // h staging: 128 rows x RPW
#define SMHV_OFF   (H_OFF + 32768)         // 2KB, inside h region (time-disjoint)
#define OWN_OFF    (H_OFF + 40960)         // 8KB own-quarter, inside h region
#define REMOTE_OFF (H_OFF + 128 * RPW)     // 202752, dedicated 3x8KB
#define REC_SMEM   (REMOTE_OFF + 3 * 8192) // 227328
#define TX_BYTES   (3 * 8192)              // remote partial bytes per step

__global__ __launch_bounds__(256, 1) __cluster_dims__(4, 1, 1)
void lstm_mma_kernel(
    const float* __restrict__ W,   // W_hh [4096,1024] fp32
    float* __restrict__ out,       // fp32 out (nullptr -> emit bf16 A hi/lo)
    float* __restrict__ hn,
    float* __restrict__ cn)
{
    extern __shared__ char sm[];
    __shared__ __align__(8) u64 s_mbar[2];   // [0]=full (tx), [1]=free (cnt 3)
    const uint32_t smW = smem_u32(sm);
    const uint32_t smH = smW + H_OFF;
    float* ownb  = reinterpret_cast<float*>(sm + OWN_OFF);
    float* rems  = reinterpret_cast<float*>(sm + REMOTE_OFF);
    float* smHv  = reinterpret_cast<float*>(sm + SMHV_OFF);

    const int tid = threadIdx.x;
    const int wid = tid >> 5;
    const int lane = tid & 31;
    const int grp = blockIdx.x >> 2;     // 0..31
    const int r   = blockIdx.x & 3;      // k-slice == cluster rank
    const int wr  = wid & 3;             // warp row group (= destination rank)
    const int wc  = wid >> 2;            // warp col group

    const uint32_t mb_full = smem_u32(&s_mbar[0]);
    const uint32_t mb_free = smem_u32(&s_mbar[1]);

    if (tid == 0) {
        MBAR_INIT(mb_full, 1);
        MBAR_INIT(mb_free, 3);
    }

    // ---- Stage W_hh slice into SMEM (hi/lo), rows = u*4 + gate ----
    {
        const int row = tid >> 1;
        const int half = tid & 1;
        const int u = row >> 2, gg = row & 3;
        const float* src = W + ((size_t)(gg * HID + grp * 32 + u)) * HID + r * KSL
                         + half * 128;
        __nv_bfloat16* dh = reinterpret_cast<__nv_bfloat16*>(sm + row * RPW) + half * 128;
        __nv_bfloat16* dl = reinterpret_cast<__nv_bfloat16*>(sm + (128 + row) * RPW) + half * 128;
        for (int k = 0; k < 128; k++) {
            float v = src[k];
            __nv_bfloat16 h = __float2bfloat16_rn(v);
            dh[k] = h;
            dl[k] = __float2bfloat16_rn(v - __bfloat162float(h));
        }
    }
    __syncthreads();
    CLUSTER_SYNC();     // all mbar inits visible cluster-wide

    // Pre-arm free phase 0: arrive once on each of my 3 peers' free mbar.
    if (tid < 3) {
        const int peer = (r + 1 + tid) & 3;
        MBAR_ARRIVE_REMOTE(mapa_rank(mb_free, peer));
    }

    const int bq = tid & 63;
    const int uq = tid >> 6;
    float cst[2] = {0.f, 0.f};

    // remote partial destination + its mbar (only used when wr != r)
    const int ridx = (r < wr) ? r : r - 1;   // my slot index in receiver wr
    const uint32_t rem_dst = mapa_rank(smW + REMOTE_OFF + (uint32_t)(ridx * 8192), wr);
    const uint32_t rem_bar = mapa_rank(mb_full, wr);

    for (int s = 0; s < SEQ; s++) {
        const int cb = s % 3;
        const int nb3 = (s + 1) % 3;
        const unsigned par = (unsigned)(s & 1);

        // arm this step's incoming-partials expectation
        if (tid == 0) MBAR_EXPECT_TX(mb_full, TX_BYTES);

        // ---- Prefetch x-projection (independent of h) ----
        float pv[2][4];
#pragma unroll
        for (int p = 0; p < 2; p++) {
            const int u_local = r * 8 + uq + p * 4;
            const int j = grp * 32 + u_local;
            const float* pp = g_proj + ((size_t)(s * BATCH + bq)) * G4 + j;
#pragma unroll
            for (int gg = 0; gg < 4; gg++)
                pv[p][gg] = __ldg(&pp[gg * HID]);
        }

        // ---- Wait for the 8 source groups' h of step s-1 (acquire) ----
        if (s > 0) {
            if (tid < 8) {
                const unsigned tgt = 4u * (unsigned)s;
                const unsigned* ad = &g_done[8 * r + tid];
                unsigned v;
                for (;;) {
                    asm volatile("ld.acquire.gpu.global.u32 %0, [%1];"
                                 : "=r"(v) : "l"(ad));
                    if (v >= tgt) break;
                    __nanosleep(32);
                }
            }
            __syncthreads();
        }

        // ---- Stage h slice (64 rows x 256 k, hi+lo) via cp.async ----
#pragma unroll
        for (int t = 0; t < 16; t++) {
            const int idx = tid + t * 256;       // 0..4095
            const int arr = idx >> 11;           // 0=hi 1=lo
            const int rem = idx & 2047;
            const int row = rem >> 5;            // batch row
            const int kc = rem & 31;             // 16B chunk
            const __nv_bfloat16* g =
                (arr ? g_hl[cb] : g_hh[cb]) + row * HID + r * KSL + kc * 8;
            CP_ASYNC16(smH + arr * (64 * RPW) + row * RPW + kc * 16, g);
        }
        CP_COMMIT();
        CP_WAIT0();
        __syncthreads();

        // ---- MMA: C[128,64] partial over k-slice, bf16x3 ----
        float acc[2][4][4];
#pragma unroll
        for (int mt = 0; mt < 2; mt++)
#pragma unroll
            for (int nt = 0; nt < 4; nt++)
#pragma unroll
                for (int c = 0; c < 4; c++) acc[mt][nt][c] = 0.f;

#pragma unroll
        for (int kk = 0; kk < 16; kk++) {
            const uint32_t aoff = (lane & 15) * RPW + (lane >> 4) * 16 + kk * 32;

            uint32_t awh[2][4], awl[2][4];
#pragma unroll
            for (int mt = 0; mt < 2; mt++) {
                const uint32_t ar = (wr * 32 + mt * 16) * RPW;
                ldsm4(awh[mt], smW + ar + aoff);
                ldsm4(awl[mt], smW + 128 * RPW + ar + aoff);
            }
            uint32_t bh4[2][4], bl4[2][4];
#pragma unroll
            for (int p = 0; p < 2; p++) {
                const uint32_t brow =
                    (uint32_t)(wc * 32 + p * 16 + ((lane >> 4) & 1) * 8 + (lane & 7)) * RPW
                    + ((lane >> 3) & 1) * 16 + kk * 32;
                ldsm4(bh4[p], smH + brow);
                ldsm4(bl4[p], smH + 64 * RPW + brow);
            }
#pragma unroll
            for (int mt = 0; mt < 2; mt++)
#pragma unroll
                for (int nt = 0; nt < 4; nt++) {
                    const uint32_t* bh = &bh4[nt >> 1][(nt & 1) * 2];
                    const uint32_t* bl = &bl4[nt >> 1][(nt & 1) * 2];
                    mma16816(acc[mt][nt], awh[mt], bh);
                    mma16816(acc[mt][nt], awh[mt], bl);
                    mma16816(acc[mt][nt], awl[mt], bh);
                }
        }

        // ---- all warps done reading h staging before ownb (aliased) write ----
        __syncthreads();

        // ---- point-to-point: wait my receivers consumed my previous partials
        //      (satisfied early; absorbs inter-rank skew), then exchange ----
        if (wr == r) {
            // own quarter: local stores, off the DSMEM port
#pragma unroll
            for (int mt = 0; mt < 2; mt++) {
                const int rl = mt * 16 + (lane >> 2);
#pragma unroll
                for (int nt = 0; nt < 4; nt++) {
                    const int col = wc * 32 + nt * 8 + (lane & 3) * 2;
                    *reinterpret_cast<float2*>(&ownb[rl * 64 + col]) =
                        make_float2(acc[mt][nt][0], acc[mt][nt][1]);
                    *reinterpret_cast<float2*>(&ownb[(rl + 8) * 64 + col]) =
                        make_float2(acc[mt][nt][2], acc[mt][nt][3]);
                }
            }
        } else {
            MBAR_WAIT(mb_free, par);
#pragma unroll
            for (int mt = 0; mt < 2; mt++) {
                const int rl = mt * 16 + (lane >> 2);
#pragma unroll
                for (int nt = 0; nt < 4; nt++) {
                    const int col = wc * 32 + nt * 8 + (lane & 3) * 2;
                    st_async64(rem_dst + (uint32_t)(rl * 256 + col * 4),
                               acc[mt][nt][0], acc[mt][nt][1], rem_bar);
                    st_async64(rem_dst + (uint32_t)((rl + 8) * 256 + col * 4),
                               acc[mt][nt][2], acc[mt][nt][3], rem_bar);
                }
            }
        }
        __syncthreads();          // ownb visible to all warps

        // ---- wait for the 3 peers' partials (tx-complete) ----
        MBAR_WAIT(mb_full, par);

        // ---- Reduce (own local + 3 remote slots) + elementwise ----
#pragma unroll
        for (int p = 0; p < 2; p++) {
            const int u_idx = uq + p * 4;
            const int u_local = r * 8 + u_idx;
            const int j = grp * 32 + u_local;
            float gate[4];
#pragma unroll
            for (int gg = 0; gg < 4; gg++) {
                const int off = (u_idx * 4 + gg) * 64 + bq;
                float t = ownb[off];
                t += rems[off];
                t += rems[2048 + off];
                t += rems[4096 + off];
                gate[gg] = t + pv[p][gg];
            }
            const float gi = sigmoidf_(gate[0]);
            const float gf = sigmoidf_(gate[1]);
            const float gG = tanhf_(gate[2]);
            const float go = sigmoidf_(gate[3]);
            const float cnew = gf * cst[p] + gi * gG;
            cst[p] = cnew;
            const float hv = go * tanhf_(cnew);
            smHv[u_idx * 64 + bq] = hv;
            if (s == SEQ - 1) {
                hn[bq * HID + j] = hv;
                cn[bq * HID + j] = cnew;
            }
        }
        __syncthreads();          // all threads done reading rems + smHv filled

        // slots consumed -> release my 3 producers for the next step
        if (tid < 3) {
            const int peer = (r + 1 + tid) & 3;
            MBAR_ARRIVE_REMOTE(mapa_rank(mb_free, peer));
        }

        // ---- h hi/lo stores FIRST (roles 0,1), then publish, then out ----
        const int j0 = grp * 32 + r * 8;
        const int role = tid >> 6;
        const int b = tid & 63;
        float hv8[8];
#pragma unroll
        for (int u = 0; u < 8; u++) hv8[u] = smHv[u * 64 + b];

        if (role == 0) {
            __nv_bfloat16 h8[8];
#pragma unroll
            for (int u = 0; u < 8; u++) h8[u] = __float2bfloat16_rn(hv8[u]);
            *reinterpret_cast<uint4*>(&g_hh[nb3][b * HID + j0]) =
                *reinterpret_cast<uint4*>(h8);
        } else if (role == 1) {
            __nv_bfloat16 l8[8];
#pragma unroll
            for (int u = 0; u < 8; u++) {
                __nv_bfloat16 h = __float2bfloat16_rn(hv8[u]);
                l8[u] = __float2bfloat16_rn(hv8[u] - __bfloat162float(h));
            }
            *reinterpret_cast<uint4*>(&g_hl[nb3][b * HID + j0]) =
                *reinterpret_cast<uint4*>(l8);
        }
        __syncthreads();

        // ---- Release publish: group counter (h is visible) ----
        if (tid == 0)
            asm volatile("red.release.gpu.global.add.u32 [%0], %1;"
                         :: "l"(&g_done[grp]), "r"(1u) : "memory");

        // ---- Layer output writes (off the inter-group critical path) ----
        if (role == 2) {
            if (out) {
                float* o = &out[((size_t)(s * BATCH + b)) * HID + j0];
                *reinterpret_cast<float4*>(o) =
                    make_float4(hv8[0], hv8[1], hv8[2], hv8[3]);
                *reinterpret_cast<float4*>(o + 4) =
                    make_float4(hv8[4], hv8[5], hv8[6], hv8[7]);
            } else {
                __nv_bfloat16 h8[8];
#pragma unroll
                for (int u = 0; u < 8; u++) h8[u] = __float2bfloat16_rn(hv8[u]);
                *reinterpret_cast<uint4*>(
                    &g_Ahi[((size_t)(s * BATCH + b)) * HID + j0]) =
                    *reinterpret_cast<uint4*>(h8);
            }
        } else if (role == 3) {
            if (!out) {
                __nv_bfloat16 l8[8];
#pragma unroll
                for (int u = 0; u < 8; u++) {
                    __nv_bfloat16 h = __float2bfloat16_rn(hv8[u]);
                    l8[u] = __float2bfloat16_rn(hv8[u] - __bfloat162float(h));
                }
                *reinterpret_cast<uint4*>(
                    &g_Alo[((size_t)(s * BATCH + b)) * HID + j0]) =
                    *reinterpret_cast<uint4*>(l8);
            }
        }
        __syncthreads();
    }
    // no CTA may exit while peers could still st.async into it
    CLUSTER_SYNC();
}

// ---------------------------------------------------------------------------
// Launch
// ---------------------------------------------------------------------------
extern "C" void kernel_launch(void* const* d_in, const int* in_sizes, int n_in,
                              void* d_out, int out_size)
{
    const float* x     = (const float*)d_in[0];
    const float* Wih0  = (const float*)d_in[1];
    const float* Whh0  = (const float*)d_in[2];
    const float* bih0  = (const float*)d_in[3];
    const float* bhh0  = (const float*)d_in[4];
    const float* Wih1  = (const float*)d_in[5];
    const float* Whh1  = (const float*)d_in[6];
    const float* bih1  = (const float*)d_in[7];
    const float* bhh1  = (const float*)d_in[8];

    float* out1 = (float*)d_out;
    float* hn   = out1 + (size_t)SEQ * BATCH * HID;
    float* cn   = hn + 2 * BATCH * HID;

    cudaFuncSetAttribute(mma_gemm_kernel,
                         cudaFuncAttributeMaxDynamicSharedMemorySize, GEMM_SMEM);
    cudaFuncSetAttribute(lstm_mma_kernel,
                         cudaFuncAttributeMaxDynamicSharedMemorySize, REC_SMEM);

    __nv_bfloat16 *Ahi, *Alo, *Whi, *Wlo;
    cudaGetSymbolAddress((void**)&Ahi, g_Ahi);
    cudaGetSymbolAddress((void**)&Alo, g_Alo);
    cudaGetSymbolAddress((void**)&Whi, g_Whi);
    cudaGetSymbolAddress((void**)&Wlo, g_Wlo);

    dim3 mgrid(MROWS / 128, G4 / 128);

    // ---- Layer 0 ----
    split_kernel<<<2048, 256>>>(x, Ahi, Alo, (MROWS * HID) / 4);
    split_kernel<<<512, 256>>>(Wih0, Whi, Wlo, (G4 * HID) / 4);
    zero_state_kernel<<<64, 256>>>();
    mma_gemm_kernel<<<mgrid, 256, GEMM_SMEM>>>(bih0, bhh0);
    lstm_mma_kernel<<<128, 256, REC_SMEM>>>(Whh0, nullptr, hn, cn);

    // ---- Layer 1 ----
    split_kernel<<<512, 256>>>(Wih1, Whi, Wlo, (G4 * HID) / 4);
    zero_state_kernel<<<64, 256>>>();
    mma_gemm_kernel<<<mgrid, 256, GEMM_SMEM>>>(bih1, bhh1);
    lstm_mma_kernel<<<128, 256, REC_SMEM>>>(Whh1, out1,
                                            hn + BATCH * HID,
                                            cn + BATCH * HID);
}